// round 15
// baseline (speedup 1.0000x reference)
#include <cuda_runtime.h>
#include <cuda_fp16.h>
#include <math.h>
#include <stdint.h>

// ---------------- problem constants ----------------
#define TT      8
#define PPF     576
#define TPF     578
#define SEQ     (TT*TPF)   // 4624
#define DMODEL  768
#define VD      1024
#define NL      12
#define NH      12
#define FF      3072
#define VISROWS (TT*PPF)   // 4608

// ---------------- scratch ----------------
__device__ float  g_x  [SEQ * DMODEL];          // fp32 residual stream
__device__ __half g_h  [SEQ * DMODEL];
__device__ __half g_qkv[SEQ * 3 * DMODEL];
__device__ __half g_ctx[SEQ * DMODEL];
__device__ __half g_ff [SEQ * FF];
// fp16 copies of inputs/weights
__device__ __half g_vt  [VISROWS * VD];
__device__ __half g_wvp [DMODEL * VD];
__device__ __half g_wqkv[NL * 3 * DMODEL * DMODEL];
__device__ __half g_wao [NL * DMODEL * DMODEL];
__device__ __half g_wff1[NL * FF * DMODEL];
__device__ __half g_wff2[NL * DMODEL * FF];
__device__ __half g_wop [VD * DMODEL];

// ---------------- helpers ----------------
__device__ __forceinline__ uint32_t smem_u32(const void* p) {
    return (uint32_t)__cvta_generic_to_shared(p);
}
__device__ __forceinline__ void cpa16(uint32_t dst, const void* src, bool v) {
    asm volatile("cp.async.cg.shared.global [%0], [%1], 16, %2;"
                 :: "r"(dst), "l"(src), "r"(v ? 16u : 0u));
}
__device__ __forceinline__ void cpa_commit() { asm volatile("cp.async.commit_group;"); }
template<int N> __device__ __forceinline__ void cpa_wait() {
    asm volatile("cp.async.wait_group %0;" :: "n"(N));
}

__device__ __forceinline__ void mma16816(float* d, const uint32_t* a, uint32_t b0, uint32_t b1) {
    asm volatile(
        "mma.sync.aligned.m16n8k16.row.col.f32.f16.f16.f32 "
        "{%0,%1,%2,%3},{%4,%5,%6,%7},{%8,%9},{%0,%1,%2,%3};"
        : "+f"(d[0]), "+f"(d[1]), "+f"(d[2]), "+f"(d[3])
        : "r"(a[0]), "r"(a[1]), "r"(a[2]), "r"(a[3]), "r"(b0), "r"(b1));
}
__device__ __forceinline__ void ldsm4(uint32_t* r, uint32_t a) {
    asm volatile("ldmatrix.sync.aligned.m8n8.x4.shared.b16 {%0,%1,%2,%3}, [%4];"
                 : "=r"(r[0]), "=r"(r[1]), "=r"(r[2]), "=r"(r[3]) : "r"(a));
}
__device__ __forceinline__ void ldsm4t(uint32_t* r, uint32_t a) {
    asm volatile("ldmatrix.sync.aligned.m8n8.x4.trans.shared.b16 {%0,%1,%2,%3}, [%4];"
                 : "=r"(r[0]), "=r"(r[1]), "=r"(r[2]), "=r"(r[3]) : "r"(a));
}
__device__ __forceinline__ uint32_t packh2(float lo, float hi) {
    __half2 h = __floats2half2_rn(lo, hi);
    return *reinterpret_cast<uint32_t*>(&h);
}

// ---------------- fp32 -> fp16 prepass ----------------
__global__ void f2h_k(const float4* __restrict__ in, uint2* __restrict__ out, int n4)
{
    int i = blockIdx.x * blockDim.x + threadIdx.x;
    if (i < n4) {
        float4 v = in[i];
        uint2 o;
        o.x = packh2(v.x, v.y);
        o.y = packh2(v.z, v.w);
        out[i] = o;
    }
}

// =====================================================================
// fp16 tensor-core GEMM: BM=128, BN=TBN. 512 threads = 16 warps (4m x 4n),
// warp tile 32 x TBN/4. 6-stage ring of 32-K chunks.
// Fill split into per-chunk commits, one issued after EACH half-group's
// fragment loads (spreads the LDGSTS burst; ldsm stay ahead in L1tex).
// K must be a multiple of 64. Rows padded to 80B.
// =====================================================================
#define LDHB  80                       // smem row stride bytes (40 halves)
#define A_ST  (128 * LDHB)             // 10240 B per 32-K A stage
#define STG   6
#define GSMEM(TBN) (STG * (A_ST + (TBN) * LDHB))

template<int TBN, int ACT, bool RESID, bool MAPIN, bool FE, bool OUTH>
__global__ __launch_bounds__(512, 1)
void gemm_h(const __half* __restrict__ A, const __half* __restrict__ W,
            const float* __restrict__ bias, const float* __restrict__ resid,
            const float* __restrict__ fe, void* __restrict__ Cv,
            int M, int N, int K)
{
    constexpr int B_ST  = TBN * LDHB;        // bytes per 32-K B stage
    constexpr int WN    = TBN / 4;           // warp n-width (48 or 64)
    constexpr int NFR   = TBN / 32;          // n-frags per warp (6 or 8)
    constexpr int NP    = TBN / 64;          // 16-row ldsm groups per warp (3 or 4)

    extern __shared__ char smc[];
    const uint32_t sb = smem_u32(smc);
    const int tid = threadIdx.x, lane = tid & 31, warp = tid >> 5;
    const int m0 = blockIdx.y * 128, n0 = blockIdx.x * TBN;
    const int wm = (warp >> 2) * 32, wn = (warp & 3) * WN;
    const int g = lane >> 2, t = lane & 3;

    // cp.async assignments (512 threads): A 1 chunk/thr, B up to 2 chunks/thr
    const __half* asrc; uint32_t adst; bool aval;
    {
        int row = tid >> 2, c4 = tid & 3;
        int m = m0 + row;
        aval = m < M;
        int am = m;
        if (MAPIN) { int tt = m / PPF; am = tt * TPF + 2 + (m - tt * PPF); }
        asrc = A + (size_t)(aval ? am : 0) * K + c4 * 8;
        adst = row * LDHB + c4 * 16;
    }
    const __half* bsrc[2]; uint32_t bdst[2];
    const bool bval2 = tid < (TBN * 4 - 512);   // 2nd B chunk valid
    {
        int row = tid >> 2, c4 = tid & 3;
        bsrc[0] = W + (size_t)(n0 + row) * K + c4 * 8;
        bdst[0] = row * LDHB + c4 * 16;
        int id = tid + 512;
        int row2 = id >> 2, c42 = id & 3;
        bsrc[1] = W + (size_t)(n0 + (bval2 ? row2 : 0)) * K + c42 * 8;
        bdst[1] = row2 * LDHB + c42 * 16;
    }

    // fill one 32-K chunk; one commit
    auto fillc = [&](int ch) {
        int s = ch % STG; int kb = ch * 32;
        cpa16(sb + s * A_ST + adst, asrc + kb, aval);
        cpa16(sb + STG * A_ST + s * B_ST + bdst[0], bsrc[0] + kb, true);
        if (bval2) cpa16(sb + STG * A_ST + s * B_ST + bdst[1], bsrc[1] + kb, true);
        cpa_commit();
    };

    const int NG = K / 64;
    const int NC = K / 32;
    fillc(0); fillc(1); fillc(2); fillc(3);

    // lane fragment offsets
    const uint32_t ga = ((lane & 7) + ((lane & 8) ? 8 : 0)) * LDHB + ((lane & 16) ? 16 : 0);
    const uint32_t gb = ((lane & 7) + ((lane & 16) ? 8 : 0)) * LDHB + ((lane & 8) ? 16 : 0);

    float acc[2][NFR][4];
#pragma unroll
    for (int a = 0; a < 2; a++)
#pragma unroll
        for (int b = 0; b < NFR; b++)
#pragma unroll
            for (int c = 0; c < 4; c++) acc[a][b][c] = 0.f;

    for (int grp = 0; grp < NG; grp++) {
        cpa_wait<2>();
        __syncthreads();

#pragma unroll
        for (int hf = 0; hf < 2; hf++) {
            int ch = grp * 2 + hf; int s = ch % STG;
            const uint32_t Asb = sb + s * A_ST + wm * LDHB + ga;
            const uint32_t Bsb = sb + STG * A_ST + s * B_ST + wn * LDHB + gb;
#pragma unroll
            for (int ks = 0; ks < 2; ks++) {
                uint32_t bf[NFR][2];
#pragma unroll
                for (int p = 0; p < NP; p++) {
                    uint32_t r[4];
                    ldsm4(r, Bsb + p * 16 * LDHB + ks * 32);
                    bf[2*p][0] = r[0]; bf[2*p][1] = r[1];
                    bf[2*p+1][0] = r[2]; bf[2*p+1][1] = r[3];
                }
                uint32_t af[2][4];
#pragma unroll
                for (int mt = 0; mt < 2; mt++)
                    ldsm4(af[mt], Asb + mt * 16 * LDHB + ks * 32);
#pragma unroll
                for (int mt = 0; mt < 2; mt++)
#pragma unroll
                    for (int nt = 0; nt < NFR; nt++)
                        mma16816(acc[mt][nt], af[mt], bf[nt][0], bf[nt][1]);
            }
            // issue ONE chunk of group g+2 after this half-group's loads
            int nch = (grp + 2) * 2 + hf;
            if (nch < NC) fillc(nch);
        }
    }

    // epilogue (c-frag: rows g,g+8; cols 2t,2t+1)
#pragma unroll
    for (int mt = 0; mt < 2; mt++) {
#pragma unroll
        for (int r = 0; r < 2; r++) {
            int m = m0 + wm + mt * 16 + g + r * 8;
            if (m >= M) continue;
            int dstrow = m, tfrm = 0;
            if (FE) { tfrm = m / PPF; dstrow = tfrm * TPF + 2 + (m - tfrm * PPF); }
#pragma unroll
            for (int nt = 0; nt < NFR; nt++) {
                int n = n0 + wn + nt * 8 + t * 2;
                float v0 = acc[mt][nt][r * 2 + 0] + bias[n];
                float v1 = acc[mt][nt][r * 2 + 1] + bias[n + 1];
                if (ACT == 1) {
                    v0 = 0.5f * v0 * (1.f + erff(v0 * 0.70710678118654752f));
                    v1 = 0.5f * v1 * (1.f + erff(v1 * 0.70710678118654752f));
                }
                if (FE) { v0 += fe[tfrm * DMODEL + n]; v1 += fe[tfrm * DMODEL + n + 1]; }
                if (RESID) {
                    const float2 rr = *reinterpret_cast<const float2*>(resid + (size_t)m * N + n);
                    v0 += rr.x; v1 += rr.y;
                }
                if (OUTH) {
                    __half* Ch = (__half*)Cv;
                    *reinterpret_cast<uint32_t*>(Ch + (size_t)dstrow * N + n) = packh2(v0, v1);
                } else {
                    float* Cf = (float*)Cv;
                    *reinterpret_cast<float2*>(Cf + (size_t)dstrow * N + n) = make_float2(v0, v1);
                }
            }
        }
    }
}

// =====================================================================
// fp16 flash attention, frame block-causal, cp.async 3-stage KV pipe.
// Block: 128 q x 1 head, 128 threads = 4 warps x 32 q rows.
// 3 CTAs/SM: grid 37x12 = 444 = 148 SMs x 3 -> one perfect wave.
// KV fill issued AFTER the QK MMA block.
// =====================================================================
#define ALDB 144                           // smem row stride bytes (72 halves)
#define QSM  (128 * ALDB)                  // 18432
#define KST  (64 * ALDB)                   // 9216
#define ATTN_SMEM (QSM + 3 * KST * 2)      // 73728

__global__ __launch_bounds__(128, 3)
void attn_h(const __half* __restrict__ qkv, __half* __restrict__ ctx)
{
    extern __shared__ char smc[];
    const uint32_t sb = smem_u32(smc);
    const uint32_t Qb = sb;
    const int q0 = (gridDim.x - 1 - blockIdx.x) * 128;   // heavy tiles first
    const int h  = blockIdx.y;
    const int tid = threadIdx.x, lane = tid & 31, warp = tid >> 5;
    const int g = lane >> 2, t = lane & 3;
    const int wq = warp * 32;

    // Q load: 128 rows x 8 chunks = 1024 -> 8/thread
#pragma unroll
    for (int i = 0; i < 8; i++) {
        int id = tid + i * 128; int row = id >> 3; int c4 = id & 7;
        int q = q0 + row;
        cpa16(Qb + row * ALDB + c4 * 16,
              qkv + (size_t)(q < SEQ ? q : 0) * 2304 + h * 64 + c4 * 8, q < SEQ);
    }
    cpa_commit();

    auto issueKV = [&](int tIdx) {
        int s = tIdx % 3; int k0 = tIdx * 64;
        uint32_t Kb = sb + QSM + s * KST;
        uint32_t Vb = sb + QSM + 3 * KST + s * KST;
#pragma unroll
        for (int i = 0; i < 4; i++) {
            int id = tid + i * 128; int row = id >> 3; int c4 = id & 7;
            int k = k0 + row;
            bool v = k < SEQ;
            const __half* base = qkv + (size_t)(v ? k : 0) * 2304 + h * 64 + c4 * 8;
            cpa16(Kb + row * ALDB + c4 * 16, base + 768,  v);
            cpa16(Vb + row * ALDB + c4 * 16, base + 1536, v);
        }
        cpa_commit();
    };

    int qmax = min(q0 + 127, SEQ - 1);
    int kv_end = min(SEQ, (qmax / TPF + 1) * TPF);
    const int T = (kv_end + 63) / 64;

    issueKV(0);
    issueKV(1);

    // lane fragment offsets
    const uint32_t qa = ((lane & 7) + ((lane & 8) ? 8 : 0)) * ALDB + ((lane & 16) ? 16 : 0);
    const uint32_t kb = ((lane & 7) + ((lane & 16) ? 8 : 0)) * ALDB + ((lane & 8) ? 16 : 0);
    const uint32_t va = ((lane & 7) + ((lane & 8) ? 8 : 0)) * ALDB + ((lane & 16) ? 16 : 0);

    // hoist Q fragments (3 groups in flight: Q, KV0, KV1 -> wait all but 2)
    cpa_wait<2>();
    __syncthreads();
    uint32_t qf[4][2][4];
#pragma unroll
    for (int kd = 0; kd < 4; kd++)
#pragma unroll
        for (int mt = 0; mt < 2; mt++)
            ldsm4(qf[kd][mt], Qb + qa + (wq + mt * 16) * ALDB + kd * 32);

    float o[2][8][4];
#pragma unroll
    for (int m = 0; m < 2; m++)
#pragma unroll
        for (int a = 0; a < 8; a++)
#pragma unroll
            for (int b = 0; b < 4; b++) o[m][a][b] = 0.f;
    float mrow[2][2] = {{-1e30f,-1e30f},{-1e30f,-1e30f}};
    float lrow[2][2] = {{0.f,0.f},{0.f,0.f}};

    int qlim[2][2];
#pragma unroll
    for (int mt = 0; mt < 2; mt++)
#pragma unroll
        for (int r = 0; r < 2; r++) {
            int qrow = q0 + wq + mt * 16 + g + r * 8;
            qlim[mt][r] = (qrow / TPF + 1) * TPF;
        }
    int qlim_w = ((q0 + wq) / TPF + 1) * TPF;

    for (int ti = 0; ti < T; ti++) {
        cpa_wait<1>();
        __syncthreads();

        const uint32_t Kb0 = sb + QSM + (ti % 3) * KST;
        const uint32_t Vb0 = sb + QSM + 3 * KST + (ti % 3) * KST;
        const int k0 = ti * 64;

        // S = Q @ K^T  (m=32q, n=64 keys, k=64 d)
        float sacc[2][8][4];
#pragma unroll
        for (int m = 0; m < 2; m++)
#pragma unroll
            for (int a = 0; a < 8; a++)
#pragma unroll
                for (int b = 0; b < 4; b++) sacc[m][a][b] = 0.f;

#pragma unroll
        for (int kd = 0; kd < 4; kd++) {
            uint32_t bf[8][2];
#pragma unroll
            for (int p = 0; p < 4; p++) {
                uint32_t r[4];
                ldsm4(r, Kb0 + kb + p * 16 * ALDB + kd * 32);
                bf[2*p][0] = r[0]; bf[2*p][1] = r[1];
                bf[2*p+1][0] = r[2]; bf[2*p+1][1] = r[3];
            }
#pragma unroll
            for (int mt = 0; mt < 2; mt++)
#pragma unroll
                for (int nt = 0; nt < 8; nt++)
                    mma16816(sacc[mt][nt], qf[kd][mt], bf[nt][0], bf[nt][1]);
        }

        // issue next KV fill AFTER the K fragment loads + QK MMAs
        if (ti + 2 < T) issueKV(ti + 2);

        // scale
#pragma unroll
        for (int m = 0; m < 2; m++)
#pragma unroll
            for (int a = 0; a < 8; a++)
#pragma unroll
                for (int b = 0; b < 4; b++) sacc[m][a][b] *= 0.125f;

        // frame-causal mask (boundary tiles only)
        if (k0 + 63 >= qlim_w) {
#pragma unroll
            for (int mt = 0; mt < 2; mt++)
#pragma unroll
                for (int nt = 0; nt < 8; nt++) {
                    int kc = k0 + nt * 8 + t * 2;
                    if (kc     >= qlim[mt][0]) sacc[mt][nt][0] = -1e30f;
                    if (kc + 1 >= qlim[mt][0]) sacc[mt][nt][1] = -1e30f;
                    if (kc     >= qlim[mt][1]) sacc[mt][nt][2] = -1e30f;
                    if (kc + 1 >= qlim[mt][1]) sacc[mt][nt][3] = -1e30f;
                }
        }

        // online softmax (per mt: rows g, g+8)
#pragma unroll
        for (int mt = 0; mt < 2; mt++)
#pragma unroll
            for (int r = 0; r < 2; r++) {
                float mx = -1e30f;
#pragma unroll
                for (int nt = 0; nt < 8; nt++)
                    mx = fmaxf(mx, fmaxf(sacc[mt][nt][r * 2], sacc[mt][nt][r * 2 + 1]));
                mx = fmaxf(mx, __shfl_xor_sync(0xffffffffu, mx, 1));
                mx = fmaxf(mx, __shfl_xor_sync(0xffffffffu, mx, 2));
                float mnew = fmaxf(mrow[mt][r], mx);
                float scl = __expf(mrow[mt][r] - mnew);
                mrow[mt][r] = mnew;
                float rs = 0.f;
#pragma unroll
                for (int nt = 0; nt < 8; nt++) {
                    float p0 = __expf(sacc[mt][nt][r * 2]     - mnew);
                    float p1 = __expf(sacc[mt][nt][r * 2 + 1] - mnew);
                    sacc[mt][nt][r * 2] = p0; sacc[mt][nt][r * 2 + 1] = p1;
                    rs += p0 + p1;
                }
                rs += __shfl_xor_sync(0xffffffffu, rs, 1);
                rs += __shfl_xor_sync(0xffffffffu, rs, 2);
                lrow[mt][r] = lrow[mt][r] * scl + rs;
#pragma unroll
                for (int nt = 0; nt < 8; nt++) { o[mt][nt][r * 2] *= scl; o[mt][nt][r * 2 + 1] *= scl; }
            }

        // O += P @ V   (P from registers: c-frag -> a-frag)
#pragma unroll
        for (int ks = 0; ks < 4; ks++) {
            uint32_t pa[2][4];
#pragma unroll
            for (int mt = 0; mt < 2; mt++) {
                pa[mt][0] = packh2(sacc[mt][2*ks][0],   sacc[mt][2*ks][1]);
                pa[mt][1] = packh2(sacc[mt][2*ks][2],   sacc[mt][2*ks][3]);
                pa[mt][2] = packh2(sacc[mt][2*ks+1][0], sacc[mt][2*ks+1][1]);
                pa[mt][3] = packh2(sacc[mt][2*ks+1][2], sacc[mt][2*ks+1][3]);
            }
            uint32_t bf[8][2];
#pragma unroll
            for (int p = 0; p < 4; p++) {
                uint32_t r[4];
                ldsm4t(r, Vb0 + va + ks * 16 * ALDB + p * 32);
                bf[2*p][0] = r[0]; bf[2*p][1] = r[1];
                bf[2*p+1][0] = r[2]; bf[2*p+1][1] = r[3];
            }
#pragma unroll
            for (int mt = 0; mt < 2; mt++)
#pragma unroll
                for (int nt = 0; nt < 8; nt++)
                    mma16816(o[mt][nt], pa[mt], bf[nt][0], bf[nt][1]);
        }
    }

    // write ctx (fp16)
#pragma unroll
    for (int mt = 0; mt < 2; mt++)
#pragma unroll
        for (int r = 0; r < 2; r++) {
            int qq = q0 + wq + mt * 16 + g + r * 8;
            if (qq >= SEQ) continue;
            float inv = 1.f / lrow[mt][r];
#pragma unroll
            for (int nt = 0; nt < 8; nt++) {
                __half* dst = ctx + (size_t)qq * DMODEL + h * 64 + nt * 8 + t * 2;
                *reinterpret_cast<uint32_t*>(dst) =
                    packh2(o[mt][nt][r * 2] * inv, o[mt][nt][r * 2 + 1] * inv);
            }
        }
}

// =====================================================================
// LayerNorm: warp-per-row (8 rows / 256-thread block), shfl-only.
// =====================================================================
__global__ __launch_bounds__(256)
void ln_kernel(const float* __restrict__ x, const float* __restrict__ g,
               const float* __restrict__ b, __half* __restrict__ y)
{
    const int warp = threadIdx.x >> 5, lane = threadIdx.x & 31;
    const int row = blockIdx.x * 8 + warp;
    const float4* xr = reinterpret_cast<const float4*>(x + (size_t)row * DMODEL);
    float4 v[6];
    float s = 0.f;
#pragma unroll
    for (int i = 0; i < 6; i++) {
        v[i] = xr[lane + i * 32];
        s += v[i].x + v[i].y + v[i].z + v[i].w;
    }
#pragma unroll
    for (int o = 16; o; o >>= 1) s += __shfl_xor_sync(0xffffffffu, s, o);
    float mu = s * (1.f / DMODEL);
    float vs = 0.f;
#pragma unroll
    for (int i = 0; i < 6; i++) {
        float dx = v[i].x - mu, dy = v[i].y - mu, dz = v[i].z - mu, dw = v[i].w - mu;
        vs += dx*dx + dy*dy + dz*dz + dw*dw;
    }
#pragma unroll
    for (int o = 16; o; o >>= 1) vs += __shfl_xor_sync(0xffffffffu, vs, o);
    float rstd = rsqrtf(vs * (1.f / DMODEL) + 1e-5f);
    const float4* g4 = reinterpret_cast<const float4*>(g);
    const float4* b4 = reinterpret_cast<const float4*>(b);
    uint2* y2 = reinterpret_cast<uint2*>(y + (size_t)row * DMODEL);
#pragma unroll
    for (int i = 0; i < 6; i++) {
        float4 gg = g4[lane + i * 32];
        float4 bb = b4[lane + i * 32];
        uint2 out;
        out.x = packh2((v[i].x - mu) * rstd * gg.x + bb.x, (v[i].y - mu) * rstd * gg.y + bb.y);
        out.y = packh2((v[i].z - mu) * rstd * gg.z + bb.z, (v[i].w - mu) * rstd * gg.w + bb.w);
        y2[lane + i * 32] = out;
    }
}

// =====================================================================
// action/state embed + RoPE (writes fp32 x)
// =====================================================================
__global__ void act_state_embed(const float* __restrict__ actions,
                                const float* __restrict__ states,
                                const float* __restrict__ aw, const float* __restrict__ ab,
                                const float* __restrict__ sw, const float* __restrict__ sb,
                                float* __restrict__ x)
{
    int t = blockIdx.x >> 1;
    int which = blockIdx.x & 1;
    const float* inp = (which ? states : actions) + t * 7;
    const float* w   = which ? sw : aw;
    const float* bbv = which ? sb : ab;

    int f  = threadIdx.x;
    int de = 2 * f, dd = 2 * f + 1;
    float e = bbv[de], o = bbv[dd];
#pragma unroll
    for (int a = 0; a < 7; a++) {
        e = fmaf(inp[a], w[de * 7 + a], e);
        o = fmaf(inp[a], w[dd * 7 + a], o);
    }
    float ang = (float)t * expf(-logf(10000.f) * ((float)de / (float)DMODEL));
    float c = cosf(ang), sn = sinf(ang);
    int s = t * TPF + which;
    x[(size_t)s * DMODEL + de] = e * c - o * sn;
    x[(size_t)s * DMODEL + dd] = e * sn + o * c;
}

// =====================================================================
// host launcher
// =====================================================================
static inline void h_pass(const float* in, __half* out, size_t n)
{
    int n4 = (int)(n / 4);
    f2h_k<<<(n4 + 255) / 256, 256>>>((const float4*)in, (uint2*)out, n4);
}

extern "C" void kernel_launch(void* const* d_in, const int* in_sizes, int n_in,
                              void* d_out, int out_size)
{
    const float* visual_tokens  = (const float*)d_in[0];
    const float* actions        = (const float*)d_in[1];
    const float* states         = (const float*)d_in[2];
    const float* visual_proj_w  = (const float*)d_in[3];
    const float* visual_proj_b  = (const float*)d_in[4];
    const float* action_proj_w  = (const float*)d_in[5];
    const float* action_proj_b  = (const float*)d_in[6];
    const float* state_proj_w   = (const float*)d_in[7];
    const float* state_proj_b   = (const float*)d_in[8];
    const float* frame_embed    = (const float*)d_in[9];
    const float* qkv_w          = (const float*)d_in[10];
    const float* qkv_b          = (const float*)d_in[11];
    const float* attn_out_w     = (const float*)d_in[12];
    const float* attn_out_b     = (const float*)d_in[13];
    const float* ln1_g          = (const float*)d_in[14];
    const float* ln1_b          = (const float*)d_in[15];
    const float* ff1_w          = (const float*)d_in[16];
    const float* ff1_b          = (const float*)d_in[17];
    const float* ff2_w          = (const float*)d_in[18];
    const float* ff2_b          = (const float*)d_in[19];
    const float* ln2_g          = (const float*)d_in[20];
    const float* ln2_b          = (const float*)d_in[21];
    const float* out_norm_g     = (const float*)d_in[22];
    const float* out_norm_b     = (const float*)d_in[23];
    const float* output_proj_w  = (const float*)d_in[24];
    const float* output_proj_b  = (const float*)d_in[25];

    float *x;
    __half *h, *qkvb, *ctx, *ff;
    __half *vt, *wvp, *wqkv, *wao, *wff1, *wff2, *wop;
    cudaGetSymbolAddress((void**)&x,    g_x);
    cudaGetSymbolAddress((void**)&h,    g_h);
    cudaGetSymbolAddress((void**)&qkvb, g_qkv);
    cudaGetSymbolAddress((void**)&ctx,  g_ctx);
    cudaGetSymbolAddress((void**)&ff,   g_ff);
    cudaGetSymbolAddress((void**)&vt,   g_vt);
    cudaGetSymbolAddress((void**)&wvp,  g_wvp);
    cudaGetSymbolAddress((void**)&wqkv, g_wqkv);
    cudaGetSymbolAddress((void**)&wao,  g_wao);
    cudaGetSymbolAddress((void**)&wff1, g_wff1);
    cudaGetSymbolAddress((void**)&wff2, g_wff2);
    cudaGetSymbolAddress((void**)&wop,  g_wop);

    // 192-wide variants
    cudaFuncSetAttribute(gemm_h<192,0,false,false,true ,false>, cudaFuncAttributeMaxDynamicSharedMemorySize, GSMEM(192));
    cudaFuncSetAttribute(gemm_h<192,0,false,false,false,true >, cudaFuncAttributeMaxDynamicSharedMemorySize, GSMEM(192));
    cudaFuncSetAttribute(gemm_h<192,0,true ,false,false,false>, cudaFuncAttributeMaxDynamicSharedMemorySize, GSMEM(192));
    cudaFuncSetAttribute(gemm_h<192,1,false,false,false,true >, cudaFuncAttributeMaxDynamicSharedMemorySize, GSMEM(192));
    // 256-wide variant (output head only)
    cudaFuncSetAttribute(gemm_h<256,0,false,true ,false,false>, cudaFuncAttributeMaxDynamicSharedMemorySize, GSMEM(256));
    cudaFuncSetAttribute(attn_h, cudaFuncAttributeMaxDynamicSharedMemorySize, ATTN_SMEM);

    // ---- fp16 conversion prepass; ncu profiles launch #4 -> vis GEMM there ----
    h_pass(visual_tokens, vt,   (size_t)VISROWS * VD);                 // #1
    h_pass(visual_proj_w, wvp,  (size_t)DMODEL * VD);                  // #2
    h_pass(qkv_w,         wqkv, (size_t)NL * 3 * DMODEL * DMODEL);     // #3

    const int MT  = (SEQ + 127) / 128;   // 37
    const int MTV = VISROWS / 128;       // 36

    // ---- visual proj (fused frame-embed add + scatter): launch #4 ----
    gemm_h<192,0,false,false,true,false><<<dim3(DMODEL/192, MTV), 512, GSMEM(192)>>>(
        vt, wvp, visual_proj_b, nullptr, frame_embed, x, VISROWS, DMODEL, VD);

    h_pass(attn_out_w,    wao,  (size_t)NL * DMODEL * DMODEL);         // #5
    h_pass(ff1_w,         wff1, (size_t)NL * FF * DMODEL);             // #6
    h_pass(ff2_w,         wff2, (size_t)NL * DMODEL * FF);             // #7
    h_pass(output_proj_w, wop,  (size_t)VD * DMODEL);                  // #8

    act_state_embed<<<2*TT, 384>>>(actions, states,
        action_proj_w, action_proj_b, state_proj_w, state_proj_b, x);

    // ---- transformer layers ----
    for (int i = 0; i < NL; i++) {
        ln_kernel<<<SEQ/8, 256>>>(x, ln1_g + i*DMODEL, ln1_b + i*DMODEL, h);
        gemm_h<192,0,false,false,false,true><<<dim3(3*DMODEL/192, MT), 512, GSMEM(192)>>>(
            h, wqkv + (size_t)i*3*DMODEL*DMODEL, qkv_b + (size_t)i*3*DMODEL,
            nullptr, nullptr, qkvb, SEQ, 3*DMODEL, DMODEL);
        attn_h<<<dim3(MT, NH), 128, ATTN_SMEM>>>(qkvb, ctx);
        gemm_h<192,0,true,false,false,false><<<dim3(DMODEL/192, MT), 512, GSMEM(192)>>>(
            ctx, wao + (size_t)i*DMODEL*DMODEL, attn_out_b + (size_t)i*DMODEL,
            x, nullptr, x, SEQ, DMODEL, DMODEL);
        ln_kernel<<<SEQ/8, 256>>>(x, ln2_g + i*DMODEL, ln2_b + i*DMODEL, h);
        gemm_h<192,1,false,false,false,true><<<dim3(FF/192, MT), 512, GSMEM(192)>>>(
            h, wff1 + (size_t)i*FF*DMODEL, ff1_b + (size_t)i*FF,
            nullptr, nullptr, ff, SEQ, FF, DMODEL);
        gemm_h<192,0,true,false,false,false><<<dim3(DMODEL/192, MT), 512, GSMEM(192)>>>(
            ff, wff2 + (size_t)i*DMODEL*FF, ff2_b + (size_t)i*DMODEL,
            x, nullptr, x, SEQ, DMODEL, FF);
    }

    // ---- output head ----
    ln_kernel<<<SEQ/8, 256>>>(x, out_norm_g, out_norm_b, h);
    gemm_h<256,0,false,true,false,false><<<dim3(VD/256, MTV), 512, GSMEM(256)>>>(
        h, wop, output_proj_b, nullptr, nullptr, (float*)d_out,
        VISROWS, VD, DMODEL);
}

// round 16
// speedup vs baseline: 1.1867x; 1.1867x over previous
#include <cuda_runtime.h>
#include <cuda_fp16.h>
#include <math.h>
#include <stdint.h>

// ---------------- problem constants ----------------
#define TT      8
#define PPF     576
#define TPF     578
#define SEQ     (TT*TPF)   // 4624
#define DMODEL  768
#define VD      1024
#define NL      12
#define NH      12
#define FF      3072
#define VISROWS (TT*PPF)   // 4608

// ---------------- scratch ----------------
__device__ float  g_x  [SEQ * DMODEL];          // fp32 residual stream
__device__ __half g_h  [SEQ * DMODEL];
__device__ __half g_qkv[SEQ * 3 * DMODEL];
__device__ __half g_ctx[SEQ * DMODEL];
__device__ __half g_ff [SEQ * FF];
// fp16 copies of inputs/weights
__device__ __half g_vt  [VISROWS * VD];
__device__ __half g_wvp [DMODEL * VD];
__device__ __half g_wqkv[NL * 3 * DMODEL * DMODEL];
__device__ __half g_wao [NL * DMODEL * DMODEL];
__device__ __half g_wff1[NL * FF * DMODEL];
__device__ __half g_wff2[NL * DMODEL * FF];
__device__ __half g_wop [VD * DMODEL];

// ---------------- helpers ----------------
__device__ __forceinline__ uint32_t smem_u32(const void* p) {
    return (uint32_t)__cvta_generic_to_shared(p);
}
__device__ __forceinline__ void cpa16(uint32_t dst, const void* src, bool v) {
    asm volatile("cp.async.cg.shared.global [%0], [%1], 16, %2;"
                 :: "r"(dst), "l"(src), "r"(v ? 16u : 0u));
}
__device__ __forceinline__ void cpa_commit() { asm volatile("cp.async.commit_group;"); }
template<int N> __device__ __forceinline__ void cpa_wait() {
    asm volatile("cp.async.wait_group %0;" :: "n"(N));
}

__device__ __forceinline__ void mma16816(float* d, const uint32_t* a, uint32_t b0, uint32_t b1) {
    asm volatile(
        "mma.sync.aligned.m16n8k16.row.col.f32.f16.f16.f32 "
        "{%0,%1,%2,%3},{%4,%5,%6,%7},{%8,%9},{%0,%1,%2,%3};"
        : "+f"(d[0]), "+f"(d[1]), "+f"(d[2]), "+f"(d[3])
        : "r"(a[0]), "r"(a[1]), "r"(a[2]), "r"(a[3]), "r"(b0), "r"(b1));
}
__device__ __forceinline__ void ldsm4(uint32_t* r, uint32_t a) {
    asm volatile("ldmatrix.sync.aligned.m8n8.x4.shared.b16 {%0,%1,%2,%3}, [%4];"
                 : "=r"(r[0]), "=r"(r[1]), "=r"(r[2]), "=r"(r[3]) : "r"(a));
}
__device__ __forceinline__ void ldsm4t(uint32_t* r, uint32_t a) {
    asm volatile("ldmatrix.sync.aligned.m8n8.x4.trans.shared.b16 {%0,%1,%2,%3}, [%4];"
                 : "=r"(r[0]), "=r"(r[1]), "=r"(r[2]), "=r"(r[3]) : "r"(a));
}
__device__ __forceinline__ uint32_t packh2(float lo, float hi) {
    __half2 h = __floats2half2_rn(lo, hi);
    return *reinterpret_cast<uint32_t*>(&h);
}

// ---------------- fp32 -> fp16 prepass ----------------
__global__ void f2h_k(const float4* __restrict__ in, uint2* __restrict__ out, int n4)
{
    int i = blockIdx.x * blockDim.x + threadIdx.x;
    if (i < n4) {
        float4 v = in[i];
        uint2 o;
        o.x = packh2(v.x, v.y);
        o.y = packh2(v.z, v.w);
        out[i] = o;
    }
}

// =====================================================================
// fp16 tensor-core GEMM: BM=128, BN=TBN. 512 threads = 16 warps (4m x 4n),
// warp tile 32 x TBN/4. 6-stage ring of 32-K chunks.
// Fill split into per-chunk commits, one issued after EACH half-group's
// fragment loads (spreads the LDGSTS burst; ldsm stay ahead in L1tex).
// K must be a multiple of 64. Rows padded to 80B.
// =====================================================================
#define LDHB  80                       // smem row stride bytes (40 halves)
#define A_ST  (128 * LDHB)             // 10240 B per 32-K A stage
#define STG   6
#define GSMEM(TBN) (STG * (A_ST + (TBN) * LDHB))

template<int TBN, int ACT, bool RESID, bool MAPIN, bool FE, bool OUTH>
__global__ __launch_bounds__(512, 1)
void gemm_h(const __half* __restrict__ A, const __half* __restrict__ W,
            const float* __restrict__ bias, const float* __restrict__ resid,
            const float* __restrict__ fe, void* __restrict__ Cv,
            int M, int N, int K)
{
    constexpr int B_ST  = TBN * LDHB;        // bytes per 32-K B stage
    constexpr int WN    = TBN / 4;           // warp n-width (48 or 64)
    constexpr int NFR   = TBN / 32;          // n-frags per warp (6 or 8)
    constexpr int NP    = TBN / 64;          // 16-row ldsm groups per warp (3 or 4)

    extern __shared__ char smc[];
    const uint32_t sb = smem_u32(smc);
    const int tid = threadIdx.x, lane = tid & 31, warp = tid >> 5;
    const int m0 = blockIdx.y * 128, n0 = blockIdx.x * TBN;
    const int wm = (warp >> 2) * 32, wn = (warp & 3) * WN;
    const int g = lane >> 2, t = lane & 3;

    // cp.async assignments (512 threads): A 1 chunk/thr, B up to 2 chunks/thr
    const __half* asrc; uint32_t adst; bool aval;
    {
        int row = tid >> 2, c4 = tid & 3;
        int m = m0 + row;
        aval = m < M;
        int am = m;
        if (MAPIN) { int tt = m / PPF; am = tt * TPF + 2 + (m - tt * PPF); }
        asrc = A + (size_t)(aval ? am : 0) * K + c4 * 8;
        adst = row * LDHB + c4 * 16;
    }
    const __half* bsrc[2]; uint32_t bdst[2];
    const bool bval2 = tid < (TBN * 4 - 512);   // 2nd B chunk valid
    {
        int row = tid >> 2, c4 = tid & 3;
        bsrc[0] = W + (size_t)(n0 + row) * K + c4 * 8;
        bdst[0] = row * LDHB + c4 * 16;
        int id = tid + 512;
        int row2 = id >> 2, c42 = id & 3;
        bsrc[1] = W + (size_t)(n0 + (bval2 ? row2 : 0)) * K + c42 * 8;
        bdst[1] = row2 * LDHB + c42 * 16;
    }

    // fill one 32-K chunk; one commit
    auto fillc = [&](int ch) {
        int s = ch % STG; int kb = ch * 32;
        cpa16(sb + s * A_ST + adst, asrc + kb, aval);
        cpa16(sb + STG * A_ST + s * B_ST + bdst[0], bsrc[0] + kb, true);
        if (bval2) cpa16(sb + STG * A_ST + s * B_ST + bdst[1], bsrc[1] + kb, true);
        cpa_commit();
    };

    const int NG = K / 64;
    const int NC = K / 32;
    fillc(0); fillc(1); fillc(2); fillc(3);

    // lane fragment offsets
    const uint32_t ga = ((lane & 7) + ((lane & 8) ? 8 : 0)) * LDHB + ((lane & 16) ? 16 : 0);
    const uint32_t gb = ((lane & 7) + ((lane & 16) ? 8 : 0)) * LDHB + ((lane & 8) ? 16 : 0);

    float acc[2][NFR][4];
#pragma unroll
    for (int a = 0; a < 2; a++)
#pragma unroll
        for (int b = 0; b < NFR; b++)
#pragma unroll
            for (int c = 0; c < 4; c++) acc[a][b][c] = 0.f;

    for (int grp = 0; grp < NG; grp++) {
        cpa_wait<2>();
        __syncthreads();

#pragma unroll
        for (int hf = 0; hf < 2; hf++) {
            int ch = grp * 2 + hf; int s = ch % STG;
            const uint32_t Asb = sb + s * A_ST + wm * LDHB + ga;
            const uint32_t Bsb = sb + STG * A_ST + s * B_ST + wn * LDHB + gb;
#pragma unroll
            for (int ks = 0; ks < 2; ks++) {
                uint32_t bf[NFR][2];
#pragma unroll
                for (int p = 0; p < NP; p++) {
                    uint32_t r[4];
                    ldsm4(r, Bsb + p * 16 * LDHB + ks * 32);
                    bf[2*p][0] = r[0]; bf[2*p][1] = r[1];
                    bf[2*p+1][0] = r[2]; bf[2*p+1][1] = r[3];
                }
                uint32_t af[2][4];
#pragma unroll
                for (int mt = 0; mt < 2; mt++)
                    ldsm4(af[mt], Asb + mt * 16 * LDHB + ks * 32);
#pragma unroll
                for (int mt = 0; mt < 2; mt++)
#pragma unroll
                    for (int nt = 0; nt < NFR; nt++)
                        mma16816(acc[mt][nt], af[mt], bf[nt][0], bf[nt][1]);
            }
            // issue ONE chunk of group g+2 after this half-group's loads
            int nch = (grp + 2) * 2 + hf;
            if (nch < NC) fillc(nch);
        }
    }

    // epilogue (c-frag: rows g,g+8; cols 2t,2t+1)
#pragma unroll
    for (int mt = 0; mt < 2; mt++) {
#pragma unroll
        for (int r = 0; r < 2; r++) {
            int m = m0 + wm + mt * 16 + g + r * 8;
            if (m >= M) continue;
            int dstrow = m, tfrm = 0;
            if (FE) { tfrm = m / PPF; dstrow = tfrm * TPF + 2 + (m - tfrm * PPF); }
#pragma unroll
            for (int nt = 0; nt < NFR; nt++) {
                int n = n0 + wn + nt * 8 + t * 2;
                float v0 = acc[mt][nt][r * 2 + 0] + bias[n];
                float v1 = acc[mt][nt][r * 2 + 1] + bias[n + 1];
                if (ACT == 1) {
                    v0 = 0.5f * v0 * (1.f + erff(v0 * 0.70710678118654752f));
                    v1 = 0.5f * v1 * (1.f + erff(v1 * 0.70710678118654752f));
                }
                if (FE) { v0 += fe[tfrm * DMODEL + n]; v1 += fe[tfrm * DMODEL + n + 1]; }
                if (RESID) {
                    const float2 rr = *reinterpret_cast<const float2*>(resid + (size_t)m * N + n);
                    v0 += rr.x; v1 += rr.y;
                }
                if (OUTH) {
                    __half* Ch = (__half*)Cv;
                    *reinterpret_cast<uint32_t*>(Ch + (size_t)dstrow * N + n) = packh2(v0, v1);
                } else {
                    float* Cf = (float*)Cv;
                    *reinterpret_cast<float2*>(Cf + (size_t)dstrow * N + n) = make_float2(v0, v1);
                }
            }
        }
    }
}

// =====================================================================
// fp16 flash attention, frame block-causal, cp.async 3-stage KV pipe.
// Block: 128 q x 1 head, 128 threads = 4 warps x 32 q rows.
// 2 CTAs/SM (register headroom; 3 CTAs forces spills -> R15 regression).
// KV fill issued AFTER the QK MMA block.
// =====================================================================
#define ALDB 144                           // smem row stride bytes (72 halves)
#define QSM  (128 * ALDB)                  // 18432
#define KST  (64 * ALDB)                   // 9216
#define ATTN_SMEM (QSM + 3 * KST * 2)      // 73728

__global__ __launch_bounds__(128, 2)
void attn_h(const __half* __restrict__ qkv, __half* __restrict__ ctx)
{
    extern __shared__ char smc[];
    const uint32_t sb = smem_u32(smc);
    const uint32_t Qb = sb;
    const int q0 = (gridDim.x - 1 - blockIdx.x) * 128;   // heavy tiles first
    const int h  = blockIdx.y;
    const int tid = threadIdx.x, lane = tid & 31, warp = tid >> 5;
    const int g = lane >> 2, t = lane & 3;
    const int wq = warp * 32;

    // Q load: 128 rows x 8 chunks = 1024 -> 8/thread
#pragma unroll
    for (int i = 0; i < 8; i++) {
        int id = tid + i * 128; int row = id >> 3; int c4 = id & 7;
        int q = q0 + row;
        cpa16(Qb + row * ALDB + c4 * 16,
              qkv + (size_t)(q < SEQ ? q : 0) * 2304 + h * 64 + c4 * 8, q < SEQ);
    }
    cpa_commit();

    auto issueKV = [&](int tIdx) {
        int s = tIdx % 3; int k0 = tIdx * 64;
        uint32_t Kb = sb + QSM + s * KST;
        uint32_t Vb = sb + QSM + 3 * KST + s * KST;
#pragma unroll
        for (int i = 0; i < 4; i++) {
            int id = tid + i * 128; int row = id >> 3; int c4 = id & 7;
            int k = k0 + row;
            bool v = k < SEQ;
            const __half* base = qkv + (size_t)(v ? k : 0) * 2304 + h * 64 + c4 * 8;
            cpa16(Kb + row * ALDB + c4 * 16, base + 768,  v);
            cpa16(Vb + row * ALDB + c4 * 16, base + 1536, v);
        }
        cpa_commit();
    };

    int qmax = min(q0 + 127, SEQ - 1);
    int kv_end = min(SEQ, (qmax / TPF + 1) * TPF);
    const int T = (kv_end + 63) / 64;

    issueKV(0);
    issueKV(1);

    // lane fragment offsets
    const uint32_t qa = ((lane & 7) + ((lane & 8) ? 8 : 0)) * ALDB + ((lane & 16) ? 16 : 0);
    const uint32_t kb = ((lane & 7) + ((lane & 16) ? 8 : 0)) * ALDB + ((lane & 8) ? 16 : 0);
    const uint32_t va = ((lane & 7) + ((lane & 8) ? 8 : 0)) * ALDB + ((lane & 16) ? 16 : 0);

    // hoist Q fragments (3 groups in flight: Q, KV0, KV1 -> wait all but 2)
    cpa_wait<2>();
    __syncthreads();
    uint32_t qf[4][2][4];
#pragma unroll
    for (int kd = 0; kd < 4; kd++)
#pragma unroll
        for (int mt = 0; mt < 2; mt++)
            ldsm4(qf[kd][mt], Qb + qa + (wq + mt * 16) * ALDB + kd * 32);

    float o[2][8][4];
#pragma unroll
    for (int m = 0; m < 2; m++)
#pragma unroll
        for (int a = 0; a < 8; a++)
#pragma unroll
            for (int b = 0; b < 4; b++) o[m][a][b] = 0.f;
    float mrow[2][2] = {{-1e30f,-1e30f},{-1e30f,-1e30f}};
    float lrow[2][2] = {{0.f,0.f},{0.f,0.f}};

    int qlim[2][2];
#pragma unroll
    for (int mt = 0; mt < 2; mt++)
#pragma unroll
        for (int r = 0; r < 2; r++) {
            int qrow = q0 + wq + mt * 16 + g + r * 8;
            qlim[mt][r] = (qrow / TPF + 1) * TPF;
        }
    int qlim_w = ((q0 + wq) / TPF + 1) * TPF;

    for (int ti = 0; ti < T; ti++) {
        cpa_wait<1>();
        __syncthreads();

        const uint32_t Kb0 = sb + QSM + (ti % 3) * KST;
        const uint32_t Vb0 = sb + QSM + 3 * KST + (ti % 3) * KST;
        const int k0 = ti * 64;

        // S = Q @ K^T  (m=32q, n=64 keys, k=64 d)
        float sacc[2][8][4];
#pragma unroll
        for (int m = 0; m < 2; m++)
#pragma unroll
            for (int a = 0; a < 8; a++)
#pragma unroll
                for (int b = 0; b < 4; b++) sacc[m][a][b] = 0.f;

#pragma unroll
        for (int kd = 0; kd < 4; kd++) {
            uint32_t bf[8][2];
#pragma unroll
            for (int p = 0; p < 4; p++) {
                uint32_t r[4];
                ldsm4(r, Kb0 + kb + p * 16 * ALDB + kd * 32);
                bf[2*p][0] = r[0]; bf[2*p][1] = r[1];
                bf[2*p+1][0] = r[2]; bf[2*p+1][1] = r[3];
            }
#pragma unroll
            for (int mt = 0; mt < 2; mt++)
#pragma unroll
                for (int nt = 0; nt < 8; nt++)
                    mma16816(sacc[mt][nt], qf[kd][mt], bf[nt][0], bf[nt][1]);
        }

        // issue next KV fill AFTER the K fragment loads + QK MMAs
        if (ti + 2 < T) issueKV(ti + 2);

        // scale
#pragma unroll
        for (int m = 0; m < 2; m++)
#pragma unroll
            for (int a = 0; a < 8; a++)
#pragma unroll
                for (int b = 0; b < 4; b++) sacc[m][a][b] *= 0.125f;

        // frame-causal mask (boundary tiles only)
        if (k0 + 63 >= qlim_w) {
#pragma unroll
            for (int mt = 0; mt < 2; mt++)
#pragma unroll
                for (int nt = 0; nt < 8; nt++) {
                    int kc = k0 + nt * 8 + t * 2;
                    if (kc     >= qlim[mt][0]) sacc[mt][nt][0] = -1e30f;
                    if (kc + 1 >= qlim[mt][0]) sacc[mt][nt][1] = -1e30f;
                    if (kc     >= qlim[mt][1]) sacc[mt][nt][2] = -1e30f;
                    if (kc + 1 >= qlim[mt][1]) sacc[mt][nt][3] = -1e30f;
                }
        }

        // online softmax (per mt: rows g, g+8)
#pragma unroll
        for (int mt = 0; mt < 2; mt++)
#pragma unroll
            for (int r = 0; r < 2; r++) {
                float mx = -1e30f;
#pragma unroll
                for (int nt = 0; nt < 8; nt++)
                    mx = fmaxf(mx, fmaxf(sacc[mt][nt][r * 2], sacc[mt][nt][r * 2 + 1]));
                mx = fmaxf(mx, __shfl_xor_sync(0xffffffffu, mx, 1));
                mx = fmaxf(mx, __shfl_xor_sync(0xffffffffu, mx, 2));
                float mnew = fmaxf(mrow[mt][r], mx);
                float scl = __expf(mrow[mt][r] - mnew);
                mrow[mt][r] = mnew;
                float rs = 0.f;
#pragma unroll
                for (int nt = 0; nt < 8; nt++) {
                    float p0 = __expf(sacc[mt][nt][r * 2]     - mnew);
                    float p1 = __expf(sacc[mt][nt][r * 2 + 1] - mnew);
                    sacc[mt][nt][r * 2] = p0; sacc[mt][nt][r * 2 + 1] = p1;
                    rs += p0 + p1;
                }
                rs += __shfl_xor_sync(0xffffffffu, rs, 1);
                rs += __shfl_xor_sync(0xffffffffu, rs, 2);
                lrow[mt][r] = lrow[mt][r] * scl + rs;
#pragma unroll
                for (int nt = 0; nt < 8; nt++) { o[mt][nt][r * 2] *= scl; o[mt][nt][r * 2 + 1] *= scl; }
            }

        // O += P @ V   (P from registers: c-frag -> a-frag)
#pragma unroll
        for (int ks = 0; ks < 4; ks++) {
            uint32_t pa[2][4];
#pragma unroll
            for (int mt = 0; mt < 2; mt++) {
                pa[mt][0] = packh2(sacc[mt][2*ks][0],   sacc[mt][2*ks][1]);
                pa[mt][1] = packh2(sacc[mt][2*ks][2],   sacc[mt][2*ks][3]);
                pa[mt][2] = packh2(sacc[mt][2*ks+1][0], sacc[mt][2*ks+1][1]);
                pa[mt][3] = packh2(sacc[mt][2*ks+1][2], sacc[mt][2*ks+1][3]);
            }
            uint32_t bf[8][2];
#pragma unroll
            for (int p = 0; p < 4; p++) {
                uint32_t r[4];
                ldsm4t(r, Vb0 + va + ks * 16 * ALDB + p * 32);
                bf[2*p][0] = r[0]; bf[2*p][1] = r[1];
                bf[2*p+1][0] = r[2]; bf[2*p+1][1] = r[3];
            }
#pragma unroll
            for (int mt = 0; mt < 2; mt++)
#pragma unroll
                for (int nt = 0; nt < 8; nt++)
                    mma16816(o[mt][nt], pa[mt], bf[nt][0], bf[nt][1]);
        }
    }

    // write ctx (fp16)
#pragma unroll
    for (int mt = 0; mt < 2; mt++)
#pragma unroll
        for (int r = 0; r < 2; r++) {
            int qq = q0 + wq + mt * 16 + g + r * 8;
            if (qq >= SEQ) continue;
            float inv = 1.f / lrow[mt][r];
#pragma unroll
            for (int nt = 0; nt < 8; nt++) {
                __half* dst = ctx + (size_t)qq * DMODEL + h * 64 + nt * 8 + t * 2;
                *reinterpret_cast<uint32_t*>(dst) =
                    packh2(o[mt][nt][r * 2] * inv, o[mt][nt][r * 2 + 1] * inv);
            }
        }
}

// =====================================================================
// LayerNorm: warp-per-row (8 rows / 256-thread block), shfl-only.
// =====================================================================
__global__ __launch_bounds__(256)
void ln_kernel(const float* __restrict__ x, const float* __restrict__ g,
               const float* __restrict__ b, __half* __restrict__ y)
{
    const int warp = threadIdx.x >> 5, lane = threadIdx.x & 31;
    const int row = blockIdx.x * 8 + warp;
    const float4* xr = reinterpret_cast<const float4*>(x + (size_t)row * DMODEL);
    float4 v[6];
    float s = 0.f;
#pragma unroll
    for (int i = 0; i < 6; i++) {
        v[i] = xr[lane + i * 32];
        s += v[i].x + v[i].y + v[i].z + v[i].w;
    }
#pragma unroll
    for (int o = 16; o; o >>= 1) s += __shfl_xor_sync(0xffffffffu, s, o);
    float mu = s * (1.f / DMODEL);
    float vs = 0.f;
#pragma unroll
    for (int i = 0; i < 6; i++) {
        float dx = v[i].x - mu, dy = v[i].y - mu, dz = v[i].z - mu, dw = v[i].w - mu;
        vs += dx*dx + dy*dy + dz*dz + dw*dw;
    }
#pragma unroll
    for (int o = 16; o; o >>= 1) vs += __shfl_xor_sync(0xffffffffu, vs, o);
    float rstd = rsqrtf(vs * (1.f / DMODEL) + 1e-5f);
    const float4* g4 = reinterpret_cast<const float4*>(g);
    const float4* b4 = reinterpret_cast<const float4*>(b);
    uint2* y2 = reinterpret_cast<uint2*>(y + (size_t)row * DMODEL);
#pragma unroll
    for (int i = 0; i < 6; i++) {
        float4 gg = g4[lane + i * 32];
        float4 bb = b4[lane + i * 32];
        uint2 out;
        out.x = packh2((v[i].x - mu) * rstd * gg.x + bb.x, (v[i].y - mu) * rstd * gg.y + bb.y);
        out.y = packh2((v[i].z - mu) * rstd * gg.z + bb.z, (v[i].w - mu) * rstd * gg.w + bb.w);
        y2[lane + i * 32] = out;
    }
}

// =====================================================================
// action/state embed + RoPE (writes fp32 x)
// =====================================================================
__global__ void act_state_embed(const float* __restrict__ actions,
                                const float* __restrict__ states,
                                const float* __restrict__ aw, const float* __restrict__ ab,
                                const float* __restrict__ sw, const float* __restrict__ sb,
                                float* __restrict__ x)
{
    int t = blockIdx.x >> 1;
    int which = blockIdx.x & 1;
    const float* inp = (which ? states : actions) + t * 7;
    const float* w   = which ? sw : aw;
    const float* bbv = which ? sb : ab;

    int f  = threadIdx.x;
    int de = 2 * f, dd = 2 * f + 1;
    float e = bbv[de], o = bbv[dd];
#pragma unroll
    for (int a = 0; a < 7; a++) {
        e = fmaf(inp[a], w[de * 7 + a], e);
        o = fmaf(inp[a], w[dd * 7 + a], o);
    }
    float ang = (float)t * expf(-logf(10000.f) * ((float)de / (float)DMODEL));
    float c = cosf(ang), sn = sinf(ang);
    int s = t * TPF + which;
    x[(size_t)s * DMODEL + de] = e * c - o * sn;
    x[(size_t)s * DMODEL + dd] = e * sn + o * c;
}

// =====================================================================
// host launcher
// =====================================================================
static inline void h_pass(const float* in, __half* out, size_t n)
{
    int n4 = (int)(n / 4);
    f2h_k<<<(n4 + 255) / 256, 256>>>((const float4*)in, (uint2*)out, n4);
}

extern "C" void kernel_launch(void* const* d_in, const int* in_sizes, int n_in,
                              void* d_out, int out_size)
{
    const float* visual_tokens  = (const float*)d_in[0];
    const float* actions        = (const float*)d_in[1];
    const float* states         = (const float*)d_in[2];
    const float* visual_proj_w  = (const float*)d_in[3];
    const float* visual_proj_b  = (const float*)d_in[4];
    const float* action_proj_w  = (const float*)d_in[5];
    const float* action_proj_b  = (const float*)d_in[6];
    const float* state_proj_w   = (const float*)d_in[7];
    const float* state_proj_b   = (const float*)d_in[8];
    const float* frame_embed    = (const float*)d_in[9];
    const float* qkv_w          = (const float*)d_in[10];
    const float* qkv_b          = (const float*)d_in[11];
    const float* attn_out_w     = (const float*)d_in[12];
    const float* attn_out_b     = (const float*)d_in[13];
    const float* ln1_g          = (const float*)d_in[14];
    const float* ln1_b          = (const float*)d_in[15];
    const float* ff1_w          = (const float*)d_in[16];
    const float* ff1_b          = (const float*)d_in[17];
    const float* ff2_w          = (const float*)d_in[18];
    const float* ff2_b          = (const float*)d_in[19];
    const float* ln2_g          = (const float*)d_in[20];
    const float* ln2_b          = (const float*)d_in[21];
    const float* out_norm_g     = (const float*)d_in[22];
    const float* out_norm_b     = (const float*)d_in[23];
    const float* output_proj_w  = (const float*)d_in[24];
    const float* output_proj_b  = (const float*)d_in[25];

    float *x;
    __half *h, *qkvb, *ctx, *ff;
    __half *vt, *wvp, *wqkv, *wao, *wff1, *wff2, *wop;
    cudaGetSymbolAddress((void**)&x,    g_x);
    cudaGetSymbolAddress((void**)&h,    g_h);
    cudaGetSymbolAddress((void**)&qkvb, g_qkv);
    cudaGetSymbolAddress((void**)&ctx,  g_ctx);
    cudaGetSymbolAddress((void**)&ff,   g_ff);
    cudaGetSymbolAddress((void**)&vt,   g_vt);
    cudaGetSymbolAddress((void**)&wvp,  g_wvp);
    cudaGetSymbolAddress((void**)&wqkv, g_wqkv);
    cudaGetSymbolAddress((void**)&wao,  g_wao);
    cudaGetSymbolAddress((void**)&wff1, g_wff1);
    cudaGetSymbolAddress((void**)&wff2, g_wff2);
    cudaGetSymbolAddress((void**)&wop,  g_wop);

    // 192-wide variants
    cudaFuncSetAttribute(gemm_h<192,0,false,false,true ,false>, cudaFuncAttributeMaxDynamicSharedMemorySize, GSMEM(192));
    cudaFuncSetAttribute(gemm_h<192,0,false,false,false,true >, cudaFuncAttributeMaxDynamicSharedMemorySize, GSMEM(192));
    cudaFuncSetAttribute(gemm_h<192,0,true ,false,false,false>, cudaFuncAttributeMaxDynamicSharedMemorySize, GSMEM(192));
    cudaFuncSetAttribute(gemm_h<192,1,false,false,false,true >, cudaFuncAttributeMaxDynamicSharedMemorySize, GSMEM(192));
    // 256-wide variant (output head only)
    cudaFuncSetAttribute(gemm_h<256,0,false,true ,false,false>, cudaFuncAttributeMaxDynamicSharedMemorySize, GSMEM(256));
    cudaFuncSetAttribute(attn_h, cudaFuncAttributeMaxDynamicSharedMemorySize, ATTN_SMEM);

    // ---- fp16 conversion prepass; ncu profiles launch #4 -> vis GEMM there ----
    h_pass(visual_tokens, vt,   (size_t)VISROWS * VD);                 // #1
    h_pass(visual_proj_w, wvp,  (size_t)DMODEL * VD);                  // #2
    h_pass(qkv_w,         wqkv, (size_t)NL * 3 * DMODEL * DMODEL);     // #3

    const int MT  = (SEQ + 127) / 128;   // 37
    const int MTV = VISROWS / 128;       // 36

    // ---- visual proj (fused frame-embed add + scatter): launch #4 ----
    gemm_h<192,0,false,false,true,false><<<dim3(DMODEL/192, MTV), 512, GSMEM(192)>>>(
        vt, wvp, visual_proj_b, nullptr, frame_embed, x, VISROWS, DMODEL, VD);

    h_pass(attn_out_w,    wao,  (size_t)NL * DMODEL * DMODEL);         // #5
    h_pass(ff1_w,         wff1, (size_t)NL * FF * DMODEL);             // #6
    h_pass(ff2_w,         wff2, (size_t)NL * DMODEL * FF);             // #7
    h_pass(output_proj_w, wop,  (size_t)VD * DMODEL);                  // #8

    act_state_embed<<<2*TT, 384>>>(actions, states,
        action_proj_w, action_proj_b, state_proj_w, state_proj_b, x);

    // ---- transformer layers ----
    for (int i = 0; i < NL; i++) {
        ln_kernel<<<SEQ/8, 256>>>(x, ln1_g + i*DMODEL, ln1_b + i*DMODEL, h);
        gemm_h<192,0,false,false,false,true><<<dim3(3*DMODEL/192, MT), 512, GSMEM(192)>>>(
            h, wqkv + (size_t)i*3*DMODEL*DMODEL, qkv_b + (size_t)i*3*DMODEL,
            nullptr, nullptr, qkvb, SEQ, 3*DMODEL, DMODEL);
        attn_h<<<dim3(MT, NH), 128, ATTN_SMEM>>>(qkvb, ctx);
        gemm_h<192,0,true,false,false,false><<<dim3(DMODEL/192, MT), 512, GSMEM(192)>>>(
            ctx, wao + (size_t)i*DMODEL*DMODEL, attn_out_b + (size_t)i*DMODEL,
            x, nullptr, x, SEQ, DMODEL, DMODEL);
        ln_kernel<<<SEQ/8, 256>>>(x, ln2_g + i*DMODEL, ln2_b + i*DMODEL, h);
        gemm_h<192,1,false,false,false,true><<<dim3(FF/192, MT), 512, GSMEM(192)>>>(
            h, wff1 + (size_t)i*FF*DMODEL, ff1_b + (size_t)i*FF,
            nullptr, nullptr, ff, SEQ, FF, DMODEL);
        gemm_h<192,0,true,false,false,false><<<dim3(DMODEL/192, MT), 512, GSMEM(192)>>>(
            ff, wff2 + (size_t)i*DMODEL*FF, ff2_b + (size_t)i*DMODEL,
            x, nullptr, x, SEQ, DMODEL, FF);
    }

    // ---- output head ----
    ln_kernel<<<SEQ/8, 256>>>(x, out_norm_g, out_norm_b, h);
    gemm_h<256,0,false,true,false,false><<<dim3(VD/256, MTV), 512, GSMEM(256)>>>(
        h, wop, output_proj_b, nullptr, nullptr, (float*)d_out,
        VISROWS, VD, DMODEL);
}

// round 17
// speedup vs baseline: 1.2038x; 1.0144x over previous
#include <cuda_runtime.h>
#include <cuda_fp16.h>
#include <math.h>
#include <stdint.h>

// ---------------- problem constants ----------------
#define TT      8
#define PPF     576
#define TPF     578
#define SEQ     (TT*TPF)   // 4624
#define DMODEL  768
#define VD      1024
#define NL      12
#define NH      12
#define FF      3072
#define VISROWS (TT*PPF)   // 4608

// ---------------- scratch ----------------
__device__ float  g_x  [SEQ * DMODEL];          // fp32 residual stream
__device__ __half g_h  [SEQ * DMODEL];
__device__ __half g_qkv[SEQ * 3 * DMODEL];
__device__ __half g_ctx[SEQ * DMODEL];
__device__ __half g_ff [SEQ * FF];
// fp16 copies of inputs/weights
__device__ __half g_vt  [VISROWS * VD];
__device__ __half g_wvp [DMODEL * VD];
__device__ __half g_wqkv[NL * 3 * DMODEL * DMODEL];
__device__ __half g_wao [NL * DMODEL * DMODEL];
__device__ __half g_wff1[NL * FF * DMODEL];
__device__ __half g_wff2[NL * DMODEL * FF];
__device__ __half g_wop [VD * DMODEL];

// ---------------- helpers ----------------
__device__ __forceinline__ uint32_t smem_u32(const void* p) {
    return (uint32_t)__cvta_generic_to_shared(p);
}
__device__ __forceinline__ void cpa16(uint32_t dst, const void* src, bool v) {
    asm volatile("cp.async.cg.shared.global [%0], [%1], 16, %2;"
                 :: "r"(dst), "l"(src), "r"(v ? 16u : 0u));
}
__device__ __forceinline__ void cpa_commit() { asm volatile("cp.async.commit_group;"); }
template<int N> __device__ __forceinline__ void cpa_wait() {
    asm volatile("cp.async.wait_group %0;" :: "n"(N));
}

__device__ __forceinline__ void mma16816(float* d, const uint32_t* a, uint32_t b0, uint32_t b1) {
    asm volatile(
        "mma.sync.aligned.m16n8k16.row.col.f32.f16.f16.f32 "
        "{%0,%1,%2,%3},{%4,%5,%6,%7},{%8,%9},{%0,%1,%2,%3};"
        : "+f"(d[0]), "+f"(d[1]), "+f"(d[2]), "+f"(d[3])
        : "r"(a[0]), "r"(a[1]), "r"(a[2]), "r"(a[3]), "r"(b0), "r"(b1));
}
__device__ __forceinline__ void ldsm4(uint32_t* r, uint32_t a) {
    asm volatile("ldmatrix.sync.aligned.m8n8.x4.shared.b16 {%0,%1,%2,%3}, [%4];"
                 : "=r"(r[0]), "=r"(r[1]), "=r"(r[2]), "=r"(r[3]) : "r"(a));
}
__device__ __forceinline__ void ldsm4t(uint32_t* r, uint32_t a) {
    asm volatile("ldmatrix.sync.aligned.m8n8.x4.trans.shared.b16 {%0,%1,%2,%3}, [%4];"
                 : "=r"(r[0]), "=r"(r[1]), "=r"(r[2]), "=r"(r[3]) : "r"(a));
}
__device__ __forceinline__ uint32_t packh2(float lo, float hi) {
    __half2 h = __floats2half2_rn(lo, hi);
    return *reinterpret_cast<uint32_t*>(&h);
}

// ---------------- fp32 -> fp16 prepass ----------------
__global__ void f2h_k(const float4* __restrict__ in, uint2* __restrict__ out, int n4)
{
    int i = blockIdx.x * blockDim.x + threadIdx.x;
    if (i < n4) {
        float4 v = in[i];
        uint2 o;
        o.x = packh2(v.x, v.y);
        o.y = packh2(v.z, v.w);
        out[i] = o;
    }
}

// =====================================================================
// fp16 tensor-core GEMM: BM=128, BN=TBN. 512 threads = 16 warps (4m x 4n),
// warp tile 32 x TBN/4. 6-stage ring of 32-K chunks; per-chunk fill
// commits at two points per group. Fragment loads DOUBLE-BUFFERED in
// registers: step s+1's ldsm issued before step s's MMAs (hides LDS lat).
// K must be a multiple of 64. Rows padded to 80B.
// =====================================================================
#define LDHB  80                       // smem row stride bytes (40 halves)
#define A_ST  (128 * LDHB)             // 10240 B per 32-K A stage
#define STG   6
#define GSMEM(TBN) (STG * (A_ST + (TBN) * LDHB))

template<int TBN, int ACT, bool RESID, bool MAPIN, bool FE, bool OUTH>
__global__ __launch_bounds__(512, 1)
void gemm_h(const __half* __restrict__ A, const __half* __restrict__ W,
            const float* __restrict__ bias, const float* __restrict__ resid,
            const float* __restrict__ fe, void* __restrict__ Cv,
            int M, int N, int K)
{
    constexpr int B_ST  = TBN * LDHB;        // bytes per 32-K B stage
    constexpr int WN    = TBN / 4;           // warp n-width (48 or 64)
    constexpr int NFR   = TBN / 32;          // n-frags per warp (6 or 8)
    constexpr int NP    = TBN / 64;          // 16-row ldsm groups per warp (3 or 4)

    extern __shared__ char smc[];
    const uint32_t sb = smem_u32(smc);
    const int tid = threadIdx.x, lane = tid & 31, warp = tid >> 5;
    const int m0 = blockIdx.y * 128, n0 = blockIdx.x * TBN;
    const int wm = (warp >> 2) * 32, wn = (warp & 3) * WN;
    const int g = lane >> 2, t = lane & 3;

    // cp.async assignments (512 threads): A 1 chunk/thr, B up to 2 chunks/thr
    const __half* asrc; uint32_t adst; bool aval;
    {
        int row = tid >> 2, c4 = tid & 3;
        int m = m0 + row;
        aval = m < M;
        int am = m;
        if (MAPIN) { int tt = m / PPF; am = tt * TPF + 2 + (m - tt * PPF); }
        asrc = A + (size_t)(aval ? am : 0) * K + c4 * 8;
        adst = row * LDHB + c4 * 16;
    }
    const __half* bsrc[2]; uint32_t bdst[2];
    const bool bval2 = tid < (TBN * 4 - 512);   // 2nd B chunk valid
    {
        int row = tid >> 2, c4 = tid & 3;
        bsrc[0] = W + (size_t)(n0 + row) * K + c4 * 8;
        bdst[0] = row * LDHB + c4 * 16;
        int id = tid + 512;
        int row2 = id >> 2, c42 = id & 3;
        bsrc[1] = W + (size_t)(n0 + (bval2 ? row2 : 0)) * K + c42 * 8;
        bdst[1] = row2 * LDHB + c42 * 16;
    }

    // fill one 32-K chunk; one commit
    auto fillc = [&](int ch) {
        int s = ch % STG; int kb = ch * 32;
        cpa16(sb + s * A_ST + adst, asrc + kb, aval);
        cpa16(sb + STG * A_ST + s * B_ST + bdst[0], bsrc[0] + kb, true);
        if (bval2) cpa16(sb + STG * A_ST + s * B_ST + bdst[1], bsrc[1] + kb, true);
        cpa_commit();
    };

    const int NG = K / 64;
    const int NC = K / 32;
    fillc(0); fillc(1); fillc(2); fillc(3);

    // lane fragment offsets
    const uint32_t ga = ((lane & 7) + ((lane & 8) ? 8 : 0)) * LDHB + ((lane & 16) ? 16 : 0);
    const uint32_t gb = ((lane & 7) + ((lane & 16) ? 8 : 0)) * LDHB + ((lane & 8) ? 16 : 0);

    float acc[2][NFR][4];
#pragma unroll
    for (int a = 0; a < 2; a++)
#pragma unroll
        for (int b = 0; b < NFR; b++)
#pragma unroll
            for (int c = 0; c < 4; c++) acc[a][b][c] = 0.f;

    for (int grp = 0; grp < NG; grp++) {
        cpa_wait<2>();
        __syncthreads();

        // double-buffered fragments: steps 0..3 = (hf 0..1) x (ks 0..1)
        uint32_t bf[2][NFR][2];
        uint32_t af[2][2][4];

        auto ldfrag = [&](int step, int buf) {
            int hf = step >> 1, ks = step & 1;
            int ch = grp * 2 + hf; int s = ch % STG;
            const uint32_t Asb = sb + s * A_ST + wm * LDHB + ga;
            const uint32_t Bsb = sb + STG * A_ST + s * B_ST + wn * LDHB + gb;
#pragma unroll
            for (int p = 0; p < NP; p++) {
                uint32_t r[4];
                ldsm4(r, Bsb + p * 16 * LDHB + ks * 32);
                bf[buf][2*p][0] = r[0]; bf[buf][2*p][1] = r[1];
                bf[buf][2*p+1][0] = r[2]; bf[buf][2*p+1][1] = r[3];
            }
#pragma unroll
            for (int mt = 0; mt < 2; mt++)
                ldsm4(af[buf][mt], Asb + mt * 16 * LDHB + ks * 32);
        };

        ldfrag(0, 0);
#pragma unroll
        for (int step = 0; step < 4; step++) {
            int cur = step & 1;
            if (step < 3) ldfrag(step + 1, (step + 1) & 1);
#pragma unroll
            for (int mt = 0; mt < 2; mt++)
#pragma unroll
                for (int nt = 0; nt < NFR; nt++)
                    mma16816(acc[mt][nt], af[cur][mt], bf[cur][nt][0], bf[cur][nt][1]);
            if (step == 1) { int nch = (grp + 2) * 2;     if (nch < NC) fillc(nch); }
            if (step == 3) { int nch = (grp + 2) * 2 + 1; if (nch < NC) fillc(nch); }
        }
    }

    // epilogue (c-frag: rows g,g+8; cols 2t,2t+1)
#pragma unroll
    for (int mt = 0; mt < 2; mt++) {
#pragma unroll
        for (int r = 0; r < 2; r++) {
            int m = m0 + wm + mt * 16 + g + r * 8;
            if (m >= M) continue;
            int dstrow = m, tfrm = 0;
            if (FE) { tfrm = m / PPF; dstrow = tfrm * TPF + 2 + (m - tfrm * PPF); }
#pragma unroll
            for (int nt = 0; nt < NFR; nt++) {
                int n = n0 + wn + nt * 8 + t * 2;
                float v0 = acc[mt][nt][r * 2 + 0] + bias[n];
                float v1 = acc[mt][nt][r * 2 + 1] + bias[n + 1];
                if (ACT == 1) {
                    v0 = 0.5f * v0 * (1.f + erff(v0 * 0.70710678118654752f));
                    v1 = 0.5f * v1 * (1.f + erff(v1 * 0.70710678118654752f));
                }
                if (FE) { v0 += fe[tfrm * DMODEL + n]; v1 += fe[tfrm * DMODEL + n + 1]; }
                if (RESID) {
                    const float2 rr = *reinterpret_cast<const float2*>(resid + (size_t)m * N + n);
                    v0 += rr.x; v1 += rr.y;
                }
                if (OUTH) {
                    __half* Ch = (__half*)Cv;
                    *reinterpret_cast<uint32_t*>(Ch + (size_t)dstrow * N + n) = packh2(v0, v1);
                } else {
                    float* Cf = (float*)Cv;
                    *reinterpret_cast<float2*>(Cf + (size_t)dstrow * N + n) = make_float2(v0, v1);
                }
            }
        }
    }
}

// =====================================================================
// fp16 flash attention, frame block-causal, cp.async 3-stage KV pipe.
// Block: 128 q x 1 head, 128 threads = 4 warps x 32 q rows.
// 2 CTAs/SM (3 CTAs forces register spills -> R15 regression).
// KV fill issued AFTER the QK MMA block.
// =====================================================================
#define ALDB 144                           // smem row stride bytes (72 halves)
#define QSM  (128 * ALDB)                  // 18432
#define KST  (64 * ALDB)                   // 9216
#define ATTN_SMEM (QSM + 3 * KST * 2)      // 73728

__global__ __launch_bounds__(128, 2)
void attn_h(const __half* __restrict__ qkv, __half* __restrict__ ctx)
{
    extern __shared__ char smc[];
    const uint32_t sb = smem_u32(smc);
    const uint32_t Qb = sb;
    const int q0 = (gridDim.x - 1 - blockIdx.x) * 128;   // heavy tiles first
    const int h  = blockIdx.y;
    const int tid = threadIdx.x, lane = tid & 31, warp = tid >> 5;
    const int g = lane >> 2, t = lane & 3;
    const int wq = warp * 32;

    // Q load: 128 rows x 8 chunks = 1024 -> 8/thread
#pragma unroll
    for (int i = 0; i < 8; i++) {
        int id = tid + i * 128; int row = id >> 3; int c4 = id & 7;
        int q = q0 + row;
        cpa16(Qb + row * ALDB + c4 * 16,
              qkv + (size_t)(q < SEQ ? q : 0) * 2304 + h * 64 + c4 * 8, q < SEQ);
    }
    cpa_commit();

    auto issueKV = [&](int tIdx) {
        int s = tIdx % 3; int k0 = tIdx * 64;
        uint32_t Kb = sb + QSM + s * KST;
        uint32_t Vb = sb + QSM + 3 * KST + s * KST;
#pragma unroll
        for (int i = 0; i < 4; i++) {
            int id = tid + i * 128; int row = id >> 3; int c4 = id & 7;
            int k = k0 + row;
            bool v = k < SEQ;
            const __half* base = qkv + (size_t)(v ? k : 0) * 2304 + h * 64 + c4 * 8;
            cpa16(Kb + row * ALDB + c4 * 16, base + 768,  v);
            cpa16(Vb + row * ALDB + c4 * 16, base + 1536, v);
        }
        cpa_commit();
    };

    int qmax = min(q0 + 127, SEQ - 1);
    int kv_end = min(SEQ, (qmax / TPF + 1) * TPF);
    const int T = (kv_end + 63) / 64;

    issueKV(0);
    issueKV(1);

    // lane fragment offsets
    const uint32_t qa = ((lane & 7) + ((lane & 8) ? 8 : 0)) * ALDB + ((lane & 16) ? 16 : 0);
    const uint32_t kb = ((lane & 7) + ((lane & 16) ? 8 : 0)) * ALDB + ((lane & 8) ? 16 : 0);
    const uint32_t va = ((lane & 7) + ((lane & 8) ? 8 : 0)) * ALDB + ((lane & 16) ? 16 : 0);

    // hoist Q fragments (3 groups in flight: Q, KV0, KV1 -> wait all but 2)
    cpa_wait<2>();
    __syncthreads();
    uint32_t qf[4][2][4];
#pragma unroll
    for (int kd = 0; kd < 4; kd++)
#pragma unroll
        for (int mt = 0; mt < 2; mt++)
            ldsm4(qf[kd][mt], Qb + qa + (wq + mt * 16) * ALDB + kd * 32);

    float o[2][8][4];
#pragma unroll
    for (int m = 0; m < 2; m++)
#pragma unroll
        for (int a = 0; a < 8; a++)
#pragma unroll
            for (int b = 0; b < 4; b++) o[m][a][b] = 0.f;
    float mrow[2][2] = {{-1e30f,-1e30f},{-1e30f,-1e30f}};
    float lrow[2][2] = {{0.f,0.f},{0.f,0.f}};

    int qlim[2][2];
#pragma unroll
    for (int mt = 0; mt < 2; mt++)
#pragma unroll
        for (int r = 0; r < 2; r++) {
            int qrow = q0 + wq + mt * 16 + g + r * 8;
            qlim[mt][r] = (qrow / TPF + 1) * TPF;
        }
    int qlim_w = ((q0 + wq) / TPF + 1) * TPF;

    for (int ti = 0; ti < T; ti++) {
        cpa_wait<1>();
        __syncthreads();

        const uint32_t Kb0 = sb + QSM + (ti % 3) * KST;
        const uint32_t Vb0 = sb + QSM + 3 * KST + (ti % 3) * KST;
        const int k0 = ti * 64;

        // S = Q @ K^T  (m=32q, n=64 keys, k=64 d)
        float sacc[2][8][4];
#pragma unroll
        for (int m = 0; m < 2; m++)
#pragma unroll
            for (int a = 0; a < 8; a++)
#pragma unroll
                for (int b = 0; b < 4; b++) sacc[m][a][b] = 0.f;

#pragma unroll
        for (int kd = 0; kd < 4; kd++) {
            uint32_t bf[8][2];
#pragma unroll
            for (int p = 0; p < 4; p++) {
                uint32_t r[4];
                ldsm4(r, Kb0 + kb + p * 16 * ALDB + kd * 32);
                bf[2*p][0] = r[0]; bf[2*p][1] = r[1];
                bf[2*p+1][0] = r[2]; bf[2*p+1][1] = r[3];
            }
#pragma unroll
            for (int mt = 0; mt < 2; mt++)
#pragma unroll
                for (int nt = 0; nt < 8; nt++)
                    mma16816(sacc[mt][nt], qf[kd][mt], bf[nt][0], bf[nt][1]);
        }

        // issue next KV fill AFTER the K fragment loads + QK MMAs
        if (ti + 2 < T) issueKV(ti + 2);

        // scale
#pragma unroll
        for (int m = 0; m < 2; m++)
#pragma unroll
            for (int a = 0; a < 8; a++)
#pragma unroll
                for (int b = 0; b < 4; b++) sacc[m][a][b] *= 0.125f;

        // frame-causal mask (boundary tiles only)
        if (k0 + 63 >= qlim_w) {
#pragma unroll
            for (int mt = 0; mt < 2; mt++)
#pragma unroll
                for (int nt = 0; nt < 8; nt++) {
                    int kc = k0 + nt * 8 + t * 2;
                    if (kc     >= qlim[mt][0]) sacc[mt][nt][0] = -1e30f;
                    if (kc + 1 >= qlim[mt][0]) sacc[mt][nt][1] = -1e30f;
                    if (kc     >= qlim[mt][1]) sacc[mt][nt][2] = -1e30f;
                    if (kc + 1 >= qlim[mt][1]) sacc[mt][nt][3] = -1e30f;
                }
        }

        // online softmax (per mt: rows g, g+8)
#pragma unroll
        for (int mt = 0; mt < 2; mt++)
#pragma unroll
            for (int r = 0; r < 2; r++) {
                float mx = -1e30f;
#pragma unroll
                for (int nt = 0; nt < 8; nt++)
                    mx = fmaxf(mx, fmaxf(sacc[mt][nt][r * 2], sacc[mt][nt][r * 2 + 1]));
                mx = fmaxf(mx, __shfl_xor_sync(0xffffffffu, mx, 1));
                mx = fmaxf(mx, __shfl_xor_sync(0xffffffffu, mx, 2));
                float mnew = fmaxf(mrow[mt][r], mx);
                float scl = __expf(mrow[mt][r] - mnew);
                mrow[mt][r] = mnew;
                float rs = 0.f;
#pragma unroll
                for (int nt = 0; nt < 8; nt++) {
                    float p0 = __expf(sacc[mt][nt][r * 2]     - mnew);
                    float p1 = __expf(sacc[mt][nt][r * 2 + 1] - mnew);
                    sacc[mt][nt][r * 2] = p0; sacc[mt][nt][r * 2 + 1] = p1;
                    rs += p0 + p1;
                }
                rs += __shfl_xor_sync(0xffffffffu, rs, 1);
                rs += __shfl_xor_sync(0xffffffffu, rs, 2);
                lrow[mt][r] = lrow[mt][r] * scl + rs;
#pragma unroll
                for (int nt = 0; nt < 8; nt++) { o[mt][nt][r * 2] *= scl; o[mt][nt][r * 2 + 1] *= scl; }
            }

        // O += P @ V   (P from registers: c-frag -> a-frag)
#pragma unroll
        for (int ks = 0; ks < 4; ks++) {
            uint32_t pa[2][4];
#pragma unroll
            for (int mt = 0; mt < 2; mt++) {
                pa[mt][0] = packh2(sacc[mt][2*ks][0],   sacc[mt][2*ks][1]);
                pa[mt][1] = packh2(sacc[mt][2*ks][2],   sacc[mt][2*ks][3]);
                pa[mt][2] = packh2(sacc[mt][2*ks+1][0], sacc[mt][2*ks+1][1]);
                pa[mt][3] = packh2(sacc[mt][2*ks+1][2], sacc[mt][2*ks+1][3]);
            }
            uint32_t bf[8][2];
#pragma unroll
            for (int p = 0; p < 4; p++) {
                uint32_t r[4];
                ldsm4t(r, Vb0 + va + ks * 16 * ALDB + p * 32);
                bf[2*p][0] = r[0]; bf[2*p][1] = r[1];
                bf[2*p+1][0] = r[2]; bf[2*p+1][1] = r[3];
            }
#pragma unroll
            for (int mt = 0; mt < 2; mt++)
#pragma unroll
                for (int nt = 0; nt < 8; nt++)
                    mma16816(o[mt][nt], pa[mt], bf[nt][0], bf[nt][1]);
        }
    }

    // write ctx (fp16)
#pragma unroll
    for (int mt = 0; mt < 2; mt++)
#pragma unroll
        for (int r = 0; r < 2; r++) {
            int qq = q0 + wq + mt * 16 + g + r * 8;
            if (qq >= SEQ) continue;
            float inv = 1.f / lrow[mt][r];
#pragma unroll
            for (int nt = 0; nt < 8; nt++) {
                __half* dst = ctx + (size_t)qq * DMODEL + h * 64 + nt * 8 + t * 2;
                *reinterpret_cast<uint32_t*>(dst) =
                    packh2(o[mt][nt][r * 2] * inv, o[mt][nt][r * 2 + 1] * inv);
            }
        }
}

// =====================================================================
// LayerNorm: warp-per-row (8 rows / 256-thread block), shfl-only.
// =====================================================================
__global__ __launch_bounds__(256)
void ln_kernel(const float* __restrict__ x, const float* __restrict__ g,
               const float* __restrict__ b, __half* __restrict__ y)
{
    const int warp = threadIdx.x >> 5, lane = threadIdx.x & 31;
    const int row = blockIdx.x * 8 + warp;
    const float4* xr = reinterpret_cast<const float4*>(x + (size_t)row * DMODEL);
    float4 v[6];
    float s = 0.f;
#pragma unroll
    for (int i = 0; i < 6; i++) {
        v[i] = xr[lane + i * 32];
        s += v[i].x + v[i].y + v[i].z + v[i].w;
    }
#pragma unroll
    for (int o = 16; o; o >>= 1) s += __shfl_xor_sync(0xffffffffu, s, o);
    float mu = s * (1.f / DMODEL);
    float vs = 0.f;
#pragma unroll
    for (int i = 0; i < 6; i++) {
        float dx = v[i].x - mu, dy = v[i].y - mu, dz = v[i].z - mu, dw = v[i].w - mu;
        vs += dx*dx + dy*dy + dz*dz + dw*dw;
    }
#pragma unroll
    for (int o = 16; o; o >>= 1) vs += __shfl_xor_sync(0xffffffffu, vs, o);
    float rstd = rsqrtf(vs * (1.f / DMODEL) + 1e-5f);
    const float4* g4 = reinterpret_cast<const float4*>(g);
    const float4* b4 = reinterpret_cast<const float4*>(b);
    uint2* y2 = reinterpret_cast<uint2*>(y + (size_t)row * DMODEL);
#pragma unroll
    for (int i = 0; i < 6; i++) {
        float4 gg = g4[lane + i * 32];
        float4 bb = b4[lane + i * 32];
        uint2 out;
        out.x = packh2((v[i].x - mu) * rstd * gg.x + bb.x, (v[i].y - mu) * rstd * gg.y + bb.y);
        out.y = packh2((v[i].z - mu) * rstd * gg.z + bb.z, (v[i].w - mu) * rstd * gg.w + bb.w);
        y2[lane + i * 32] = out;
    }
}

// =====================================================================
// action/state embed + RoPE (writes fp32 x)
// =====================================================================
__global__ void act_state_embed(const float* __restrict__ actions,
                                const float* __restrict__ states,
                                const float* __restrict__ aw, const float* __restrict__ ab,
                                const float* __restrict__ sw, const float* __restrict__ sb,
                                float* __restrict__ x)
{
    int t = blockIdx.x >> 1;
    int which = blockIdx.x & 1;
    const float* inp = (which ? states : actions) + t * 7;
    const float* w   = which ? sw : aw;
    const float* bbv = which ? sb : ab;

    int f  = threadIdx.x;
    int de = 2 * f, dd = 2 * f + 1;
    float e = bbv[de], o = bbv[dd];
#pragma unroll
    for (int a = 0; a < 7; a++) {
        e = fmaf(inp[a], w[de * 7 + a], e);
        o = fmaf(inp[a], w[dd * 7 + a], o);
    }
    float ang = (float)t * expf(-logf(10000.f) * ((float)de / (float)DMODEL));
    float c = cosf(ang), sn = sinf(ang);
    int s = t * TPF + which;
    x[(size_t)s * DMODEL + de] = e * c - o * sn;
    x[(size_t)s * DMODEL + dd] = e * sn + o * c;
}

// =====================================================================
// host launcher
// =====================================================================
static inline void h_pass(const float* in, __half* out, size_t n)
{
    int n4 = (int)(n / 4);
    f2h_k<<<(n4 + 255) / 256, 256>>>((const float4*)in, (uint2*)out, n4);
}

extern "C" void kernel_launch(void* const* d_in, const int* in_sizes, int n_in,
                              void* d_out, int out_size)
{
    const float* visual_tokens  = (const float*)d_in[0];
    const float* actions        = (const float*)d_in[1];
    const float* states         = (const float*)d_in[2];
    const float* visual_proj_w  = (const float*)d_in[3];
    const float* visual_proj_b  = (const float*)d_in[4];
    const float* action_proj_w  = (const float*)d_in[5];
    const float* action_proj_b  = (const float*)d_in[6];
    const float* state_proj_w   = (const float*)d_in[7];
    const float* state_proj_b   = (const float*)d_in[8];
    const float* frame_embed    = (const float*)d_in[9];
    const float* qkv_w          = (const float*)d_in[10];
    const float* qkv_b          = (const float*)d_in[11];
    const float* attn_out_w     = (const float*)d_in[12];
    const float* attn_out_b     = (const float*)d_in[13];
    const float* ln1_g          = (const float*)d_in[14];
    const float* ln1_b          = (const float*)d_in[15];
    const float* ff1_w          = (const float*)d_in[16];
    const float* ff1_b          = (const float*)d_in[17];
    const float* ff2_w          = (const float*)d_in[18];
    const float* ff2_b          = (const float*)d_in[19];
    const float* ln2_g          = (const float*)d_in[20];
    const float* ln2_b          = (const float*)d_in[21];
    const float* out_norm_g     = (const float*)d_in[22];
    const float* out_norm_b     = (const float*)d_in[23];
    const float* output_proj_w  = (const float*)d_in[24];
    const float* output_proj_b  = (const float*)d_in[25];

    float *x;
    __half *h, *qkvb, *ctx, *ff;
    __half *vt, *wvp, *wqkv, *wao, *wff1, *wff2, *wop;
    cudaGetSymbolAddress((void**)&x,    g_x);
    cudaGetSymbolAddress((void**)&h,    g_h);
    cudaGetSymbolAddress((void**)&qkvb, g_qkv);
    cudaGetSymbolAddress((void**)&ctx,  g_ctx);
    cudaGetSymbolAddress((void**)&ff,   g_ff);
    cudaGetSymbolAddress((void**)&vt,   g_vt);
    cudaGetSymbolAddress((void**)&wvp,  g_wvp);
    cudaGetSymbolAddress((void**)&wqkv, g_wqkv);
    cudaGetSymbolAddress((void**)&wao,  g_wao);
    cudaGetSymbolAddress((void**)&wff1, g_wff1);
    cudaGetSymbolAddress((void**)&wff2, g_wff2);
    cudaGetSymbolAddress((void**)&wop,  g_wop);

    // 192-wide variants
    cudaFuncSetAttribute(gemm_h<192,0,false,false,true ,false>, cudaFuncAttributeMaxDynamicSharedMemorySize, GSMEM(192));
    cudaFuncSetAttribute(gemm_h<192,0,false,false,false,true >, cudaFuncAttributeMaxDynamicSharedMemorySize, GSMEM(192));
    cudaFuncSetAttribute(gemm_h<192,0,true ,false,false,false>, cudaFuncAttributeMaxDynamicSharedMemorySize, GSMEM(192));
    cudaFuncSetAttribute(gemm_h<192,1,false,false,false,true >, cudaFuncAttributeMaxDynamicSharedMemorySize, GSMEM(192));
    // 256-wide variant (output head only)
    cudaFuncSetAttribute(gemm_h<256,0,false,true ,false,false>, cudaFuncAttributeMaxDynamicSharedMemorySize, GSMEM(256));
    cudaFuncSetAttribute(attn_h, cudaFuncAttributeMaxDynamicSharedMemorySize, ATTN_SMEM);

    // ---- fp16 conversion prepass; ncu profiles launch #4 -> vis GEMM there ----
    h_pass(visual_tokens, vt,   (size_t)VISROWS * VD);                 // #1
    h_pass(visual_proj_w, wvp,  (size_t)DMODEL * VD);                  // #2
    h_pass(qkv_w,         wqkv, (size_t)NL * 3 * DMODEL * DMODEL);     // #3

    const int MT  = (SEQ + 127) / 128;   // 37
    const int MTV = VISROWS / 128;       // 36

    // ---- visual proj (fused frame-embed add + scatter): launch #4 ----
    gemm_h<192,0,false,false,true,false><<<dim3(DMODEL/192, MTV), 512, GSMEM(192)>>>(
        vt, wvp, visual_proj_b, nullptr, frame_embed, x, VISROWS, DMODEL, VD);

    h_pass(attn_out_w,    wao,  (size_t)NL * DMODEL * DMODEL);         // #5
    h_pass(ff1_w,         wff1, (size_t)NL * FF * DMODEL);             // #6
    h_pass(ff2_w,         wff2, (size_t)NL * DMODEL * FF);             // #7
    h_pass(output_proj_w, wop,  (size_t)VD * DMODEL);                  // #8

    act_state_embed<<<2*TT, 384>>>(actions, states,
        action_proj_w, action_proj_b, state_proj_w, state_proj_b, x);

    // ---- transformer layers ----
    for (int i = 0; i < NL; i++) {
        ln_kernel<<<SEQ/8, 256>>>(x, ln1_g + i*DMODEL, ln1_b + i*DMODEL, h);
        gemm_h<192,0,false,false,false,true><<<dim3(3*DMODEL/192, MT), 512, GSMEM(192)>>>(
            h, wqkv + (size_t)i*3*DMODEL*DMODEL, qkv_b + (size_t)i*3*DMODEL,
            nullptr, nullptr, qkvb, SEQ, 3*DMODEL, DMODEL);
        attn_h<<<dim3(MT, NH), 128, ATTN_SMEM>>>(qkvb, ctx);
        gemm_h<192,0,true,false,false,false><<<dim3(DMODEL/192, MT), 512, GSMEM(192)>>>(
            ctx, wao + (size_t)i*DMODEL*DMODEL, attn_out_b + (size_t)i*DMODEL,
            x, nullptr, x, SEQ, DMODEL, DMODEL);
        ln_kernel<<<SEQ/8, 256>>>(x, ln2_g + i*DMODEL, ln2_b + i*DMODEL, h);
        gemm_h<192,1,false,false,false,true><<<dim3(FF/192, MT), 512, GSMEM(192)>>>(
            h, wff1 + (size_t)i*FF*DMODEL, ff1_b + (size_t)i*FF,
            nullptr, nullptr, ff, SEQ, FF, DMODEL);
        gemm_h<192,0,true,false,false,false><<<dim3(DMODEL/192, MT), 512, GSMEM(192)>>>(
            ff, wff2 + (size_t)i*DMODEL*FF, ff2_b + (size_t)i*DMODEL,
            x, nullptr, x, SEQ, DMODEL, FF);
    }

    // ---- output head ----
    ln_kernel<<<SEQ/8, 256>>>(x, out_norm_g, out_norm_b, h);
    gemm_h<256,0,false,true,false,false><<<dim3(VD/256, MTV), 512, GSMEM(256)>>>(
        h, wop, output_proj_b, nullptr, nullptr, (float*)d_out,
        VISROWS, VD, DMODEL);
}